// round 6
// baseline (speedup 1.0000x reference)
#include <cuda_runtime.h>
#include <cuda_fp16.h>
#include <cstdint>

// Problem constants
#define CIN   128
#define COUT  256
#define DTOT  1152     // 18 chunks * 64
#define RCH   18
#define NPIX  16384

// ---------------- device scratch (no cudaMalloc allowed) ----------------
__device__ __half   g_wqh[COUT * DTOT];   // quantized weight fp16 [m][d]
__device__ __half   g_xh[NPIX * DTOT];    // im2col hi fp16 [pix][d]  (37.7 MB)
__device__ __half   g_xl[NPIX * DTOT];    // im2col lo fp16 [pix][d]  (37.7 MB)
__device__ int      g_tab[DTOT];          // packed im2col offsets: off | (p<<20)
__device__ unsigned g_kmin, g_kmax;

// ---------------- helpers ----------------
__device__ __forceinline__ unsigned f2key(float f) {
    unsigned u = __float_as_uint(f);
    return (u & 0x80000000u) ? ~u : (u | 0x80000000u);
}
__device__ __forceinline__ float key2f(unsigned k) {
    unsigned u = (k & 0x80000000u) ? (k ^ 0x80000000u) : ~k;
    return __uint_as_float(u);
}
__device__ __forceinline__ uint32_t smem_u32(const void* p) {
    uint32_t a;
    asm("{ .reg .u64 t; cvta.to.shared.u64 t, %1; cvt.u32.u64 %0, t; }" : "=r"(a) : "l"(p));
    return a;
}

#define LDSM4(r, addr)                                                         \
    asm volatile("ldmatrix.sync.aligned.m8n8.x4.shared.b16 {%0,%1,%2,%3},[%4];"\
        : "=r"((r)[0]), "=r"((r)[1]), "=r"((r)[2]), "=r"((r)[3]) : "r"(addr))

#define MMA16816(c, a, b0v, b1v)                                               \
    asm volatile("mma.sync.aligned.m16n8k16.row.col.f32.f16.f16.f32 "          \
        "{%0,%1,%2,%3},{%4,%5,%6,%7},{%8,%9},{%0,%1,%2,%3};"                   \
        : "+f"((c)[0]), "+f"((c)[1]), "+f"((c)[2]), "+f"((c)[3])               \
        : "r"((a)[0]), "r"((a)[1]), "r"((a)[2]), "r"((a)[3]),                  \
          "r"(b0v), "r"(b1v))

#define CP16(dst, src)                                                         \
    asm volatile("cp.async.cg.shared.global [%0], [%1], 16;"                   \
        :: "r"(dst), "l"(src) : "memory")
#define CP_COMMIT() asm volatile("cp.async.commit_group;" ::: "memory")
#define CP_WAIT0()  asm volatile("cp.async.wait_group 0;" ::: "memory")

// ---------------- prep kernels ----------------
__global__ void k_init() { g_kmin = 0xFFFFFFFFu; g_kmax = 0u; }

// 288 blocks x 256 threads x float4 = 294912 elements exactly
__global__ void k_minmax(const float* __restrict__ w) {
    int idx = (blockIdx.x * 256 + threadIdx.x) * 4;
    float4 v = *(const float4*)(w + idx);
    float lmin = fminf(fminf(v.x, v.y), fminf(v.z, v.w));
    float lmax = fmaxf(fmaxf(v.x, v.y), fmaxf(v.z, v.w));
    unsigned kmin = f2key(lmin), kmax = f2key(lmax);
#pragma unroll
    for (int s = 16; s; s >>= 1) {
        kmin = min(kmin, __shfl_xor_sync(0xffffffffu, kmin, s));
        kmax = max(kmax, __shfl_xor_sync(0xffffffffu, kmax, s));
    }
    __shared__ unsigned smin[8], smax[8];
    int wid = threadIdx.x >> 5;
    if ((threadIdx.x & 31) == 0) { smin[wid] = kmin; smax[wid] = kmax; }
    __syncthreads();
    if (threadIdx.x == 0) {
#pragma unroll
        for (int i = 1; i < 8; i++) { kmin = min(kmin, smin[i]); kmax = max(kmax, smax[i]); }
        atomicMin(&g_kmin, kmin);
        atomicMax(&g_kmax, kmax);
    }
}

// 288 blocks x 1024 threads: quantize w[m][d] -> fp16 (exact small ints)
__global__ void k_quant(const float* __restrict__ w) {
    float wmin = key2f(g_kmin), wmax = key2f(g_kmax);
    float scale = 15.0f / (wmax - wmin + 1e-9f);
    int idx = blockIdx.x * 1024 + threadIdx.x;   // 294912 total
    float q = rintf(w[idx] * scale);
    q = fminf(fmaxf(q, -7.0f), 7.0f);
    g_wqh[idx] = __float2half_rn(q);
    if (idx < DTOT) {
        int c = idx / 9, p = idx - c * 9, di = p / 3, dj = p - di * 3;
        g_tab[idx] = (c * 1024 + di * 32 + dj) | (p << 20);
    }
}

// im2col + exact fp16 hi/lo split, done ONCE per (pixel, k).
// 8192 blocks x 288 threads: 2 pixels per block, 144 threads per pixel (8 k each)
__global__ void __launch_bounds__(288)
k_im2col(const float* __restrict__ inp) {
    const int sub = threadIdx.x >= 144;
    const int j = threadIdx.x - sub * 144;      // 0..143
    const int pix = blockIdx.x * 2 + sub;
    const int b = pix >> 10, hw = pix & 1023, h = hw >> 5, wc = hw & 31;
    const float* xbase = inp + (size_t)b * (CIN * 1024) + h * 32 + wc - 33;

    int vmask = 0;
#pragma unroll
    for (int di = 0; di < 3; ++di)
#pragma unroll
        for (int dj = 0; dj < 3; ++dj) {
            int hh = h + di - 1, wwp = wc + dj - 1;
            if (hh >= 0 && hh < 32 && wwp >= 0 && wwp < 32)
                vmask |= 1 << (di * 3 + dj);
        }

    const int k0 = j * 8;
    const int* tab = g_tab + k0;
    uint32_t hi4[4], lo4[4];
#pragma unroll
    for (int t = 0; t < 4; t++) {
        int e0 = tab[t * 2], e1 = tab[t * 2 + 1];
        float v0 = ((vmask >> (e0 >> 20)) & 1) ? __ldg(xbase + (e0 & 0xFFFFF)) : 0.0f;
        float v1 = ((vmask >> (e1 >> 20)) & 1) ? __ldg(xbase + (e1 & 0xFFFFF)) : 0.0f;
        __half2 hh = __floats2half2_rn(v0, v1);
        float2 hf = __half22float2(hh);
        __half2 hl = __floats2half2_rn(v0 - hf.x, v1 - hf.y);
        hi4[t] = *reinterpret_cast<uint32_t*>(&hh);
        lo4[t] = *reinterpret_cast<uint32_t*>(&hl);
    }
    size_t off = (size_t)pix * DTOT + k0;
    *reinterpret_cast<uint4*>(g_xh + off) = make_uint4(hi4[0], hi4[1], hi4[2], hi4[3]);
    *reinterpret_cast<uint4*>(g_xl + off) = make_uint4(lo4[0], lo4[1], lo4[2], lo4[3]);
}

// ---------------- main HMMA GEMM ----------------
// Block tile: 128 pixels x 128 channels, 16 warps, warp tile 32x32.
// grid = (16384/128) * (256/128) = 128 * 2 = 256 blocks.
// smem: double-buffered stages of [Ah 128x72 | Al 128x72 | B 128x72] halves.
#define SLD        72                 // halves per smem row (64 data + 8 pad)
#define ROWB       (SLD * 2)          // 144 bytes
#define MAT_BYTES  (128 * ROWB)       // 18432
#define STG_BYTES  (3 * MAT_BYTES)    // 55296
#define SMEM_DYN   (2 * STG_BYTES)    // 110592

__global__ void __launch_bounds__(512, 1)
k_gemm(float* __restrict__ out) {
    extern __shared__ char dyn[];
    const uint32_t dynb = smem_u32(dyn);

    const int tid = threadIdx.x, lane = tid & 31, wid = tid >> 5;
    const int bm = blockIdx.x >> 1;       // pixel tile (128 pixels)
    const int bn = blockIdx.x & 1;        // channel half (128 channels)
    const int b = bm >> 3;
    const int hw0 = (bm & 7) << 7;
    const int pix0 = bm * 128;
    const int m0 = bn * 128;

    // ---- copy-thread mapping: 1024 16B-chunks per matrix, 2 per thread ----
    const int row0 = tid >> 3, kg0 = tid & 7;           // chunk tid
    const int row1 = (tid + 512) >> 3, kg1 = tid & 7;   // chunk tid+512
    const __half* srcA = g_xh + (size_t)pix0 * DTOT;
    const __half* srcL = g_xl + (size_t)pix0 * DTOT;
    const __half* srcB = g_wqh + (size_t)m0 * DTOT;
    const uint32_t d0 = row0 * ROWB + kg0 * 16;
    const uint32_t d1 = row1 * ROWB + kg1 * 16;
    const size_t s0 = (size_t)row0 * DTOT + kg0 * 8;
    const size_t s1 = (size_t)row1 * DTOT + kg1 * 8;

    // ---- compute mapping: 16 warps = 4 (pixel) x 4 (channel) ----
    const int wm = wid & 3, wn = wid >> 2;
    const uint32_t offA = ((wm * 32 + (lane & 15)) * SLD + (lane >> 4) * 8) * 2;
    const uint32_t offB = ((wn * 32 + (lane & 15)) * SLD + (lane >> 4) * 8) * 2;

    // prologue: stage chunk 0 into buffer 0
    {
        const int koff = 0;
        CP16(dynb + d0, srcA + koff + s0);
        CP16(dynb + d1, srcA + koff + s1);
        CP16(dynb + MAT_BYTES + d0, srcL + koff + s0);
        CP16(dynb + MAT_BYTES + d1, srcL + koff + s1);
        CP16(dynb + 2 * MAT_BYTES + d0, srcB + koff + s0);
        CP16(dynb + 2 * MAT_BYTES + d1, srcB + koff + s1);
        CP_COMMIT();
    }

    uint32_t cnt[8];
#pragma unroll
    for (int j = 0; j < 8; j++) cnt[j] = 0;

#pragma unroll 1
    for (int c = 0; c < RCH; c++) {
        CP_WAIT0();
        __syncthreads();

        // stage chunk c+1 into the other buffer (overlaps with MMAs below)
        if (c + 1 < RCH) {
            const uint32_t sb = dynb + ((c + 1) & 1) * STG_BYTES;
            const int koff = (c + 1) * 64;
            CP16(sb + d0, srcA + koff + s0);
            CP16(sb + d1, srcA + koff + s1);
            CP16(sb + MAT_BYTES + d0, srcL + koff + s0);
            CP16(sb + MAT_BYTES + d1, srcL + koff + s1);
            CP16(sb + 2 * MAT_BYTES + d0, srcB + koff + s0);
            CP16(sb + 2 * MAT_BYTES + d1, srcB + koff + s1);
            CP_COMMIT();
        }

        // compute chunk c
        const uint32_t sb = dynb + (c & 1) * STG_BYTES;
        const uint32_t aAh0 = sb + offA, aAh1 = aAh0 + 16 * ROWB;
        const uint32_t aAl0 = aAh0 + MAT_BYTES, aAl1 = aAl0 + 16 * ROWB;
        const uint32_t aB0 = sb + 2 * MAT_BYTES + offB, aB1 = aB0 + 16 * ROWB;

        float cacc[2][4][4];
#pragma unroll
        for (int mt = 0; mt < 2; mt++)
#pragma unroll
            for (int nt = 0; nt < 4; nt++)
#pragma unroll
                for (int e = 0; e < 4; e++) cacc[mt][nt][e] = 0.0f;

#pragma unroll
        for (int ks = 0; ks < 4; ks++) {
            const uint32_t off = ks * 32;  // 16 halves
            uint32_t ah0[4], ah1[4], al0[4], al1[4], b0[4], b1[4];
            LDSM4(ah0, aAh0 + off);
            LDSM4(ah1, aAh1 + off);
            LDSM4(al0, aAl0 + off);
            LDSM4(al1, aAl1 + off);
            LDSM4(b0, aB0 + off);
            LDSM4(b1, aB1 + off);
            MMA16816(cacc[0][0], ah0, b0[0], b0[2]);
            MMA16816(cacc[0][1], ah0, b0[1], b0[3]);
            MMA16816(cacc[0][2], ah0, b1[0], b1[2]);
            MMA16816(cacc[0][3], ah0, b1[1], b1[3]);
            MMA16816(cacc[1][0], ah1, b0[0], b0[2]);
            MMA16816(cacc[1][1], ah1, b0[1], b0[3]);
            MMA16816(cacc[1][2], ah1, b1[0], b1[2]);
            MMA16816(cacc[1][3], ah1, b1[1], b1[3]);
            MMA16816(cacc[0][0], al0, b0[0], b0[2]);
            MMA16816(cacc[0][1], al0, b0[1], b0[3]);
            MMA16816(cacc[0][2], al0, b1[0], b1[2]);
            MMA16816(cacc[0][3], al0, b1[1], b1[3]);
            MMA16816(cacc[1][0], al1, b0[0], b0[2]);
            MMA16816(cacc[1][1], al1, b0[1], b0[3]);
            MMA16816(cacc[1][2], al1, b1[0], b1[2]);
            MMA16816(cacc[1][3], al1, b1[1], b1[3]);
        }

        // threshold (>= 0 -> +1) into packed byte counters
#pragma unroll
        for (int mt = 0; mt < 2; mt++)
#pragma unroll
            for (int nt = 0; nt < 4; nt++)
#pragma unroll
                for (int e = 0; e < 4; e++) {
                    int idx = mt * 16 + nt * 4 + e;
                    uint32_t one = (cacc[mt][nt][e] >= 0.0f) ? 1u : 0u;
                    cnt[idx >> 2] += one << ((idx & 3) * 8);
                }
        __syncthreads();
    }

    // ---- write counts ----
    {
        const int g = lane >> 2, t = lane & 3;
        float* obase = out + ((size_t)(b * COUT + m0 + wn * 32) << 10) + hw0;
#pragma unroll
        for (int mt = 0; mt < 2; mt++)
#pragma unroll
            for (int e2 = 0; e2 < 2; e2++) {
                int pixl = wm * 32 + mt * 16 + g + e2 * 8;
#pragma unroll
                for (int nt = 0; nt < 4; nt++)
#pragma unroll
                    for (int e1 = 0; e1 < 2; e1++) {
                        int chan = nt * 8 + 2 * t + e1;
                        int idx = mt * 16 + nt * 4 + e2 * 2 + e1;
                        float val = (float)((cnt[idx >> 2] >> ((idx & 3) * 8)) & 0xFF);
                        obase[((size_t)chan << 10) + pixl] = val;
                    }
            }
    }
}

// ---------------- launch ----------------
extern "C" void kernel_launch(void* const* d_in, const int* in_sizes, int n_in,
                              void* d_out, int out_size) {
    const float* inp = (const float*)d_in[0];  // [16,128,32,32]
    const float* wt  = (const float*)d_in[1];  // [256,128,3,3]
    float* out = (float*)d_out;                // [16,256,32,32]

    cudaFuncSetAttribute(k_gemm, cudaFuncAttributeMaxDynamicSharedMemorySize, SMEM_DYN);

    k_init<<<1, 1>>>();
    k_minmax<<<288, 256>>>(wt);
    k_quant<<<288, 1024>>>(wt);
    k_im2col<<<8192, 288>>>(inp);
    k_gemm<<<256, 512, SMEM_DYN>>>(out);
}

// round 7
// speedup vs baseline: 1.7133x; 1.7133x over previous
#include <cuda_runtime.h>
#include <cuda_fp16.h>
#include <cstdint>

// Problem constants
#define CIN   128
#define COUT  256
#define DTOT  1152     // 18 chunks * 64
#define RCH   18
#define NPIX  16384

// ---------------- device scratch (no cudaMalloc allowed) ----------------
__device__ __half   g_wqh[COUT * DTOT];   // quantized weight fp16 [m][d]
__device__ int      g_tab[DTOT];          // packed im2col offsets: off | (p<<20)
__device__ unsigned g_kmin, g_kmax;

// ---------------- helpers ----------------
__device__ __forceinline__ unsigned f2key(float f) {
    unsigned u = __float_as_uint(f);
    return (u & 0x80000000u) ? ~u : (u | 0x80000000u);
}
__device__ __forceinline__ float key2f(unsigned k) {
    unsigned u = (k & 0x80000000u) ? (k ^ 0x80000000u) : ~k;
    return __uint_as_float(u);
}
__device__ __forceinline__ uint32_t smem_u32(const void* p) {
    uint32_t a;
    asm("{ .reg .u64 t; cvta.to.shared.u64 t, %1; cvt.u32.u64 %0, t; }" : "=r"(a) : "l"(p));
    return a;
}

#define LDSM4(r, addr)                                                         \
    asm volatile("ldmatrix.sync.aligned.m8n8.x4.shared.b16 {%0,%1,%2,%3},[%4];"\
        : "=r"((r)[0]), "=r"((r)[1]), "=r"((r)[2]), "=r"((r)[3]) : "r"(addr))

#define MMA16816(c, a, b0v, b1v)                                               \
    asm volatile("mma.sync.aligned.m16n8k16.row.col.f32.f16.f16.f32 "          \
        "{%0,%1,%2,%3},{%4,%5,%6,%7},{%8,%9},{%0,%1,%2,%3};"                   \
        : "+f"((c)[0]), "+f"((c)[1]), "+f"((c)[2]), "+f"((c)[3])               \
        : "r"((a)[0]), "r"((a)[1]), "r"((a)[2]), "r"((a)[3]),                  \
          "r"(b0v), "r"(b1v))

#define CP16(dst, src)                                                         \
    asm volatile("cp.async.cg.shared.global [%0], [%1], 16;"                   \
        :: "r"(dst), "l"(src) : "memory")
#define CP_COMMIT() asm volatile("cp.async.commit_group;" ::: "memory")
#define CP_WAIT0()  asm volatile("cp.async.wait_group 0;" ::: "memory")

// ---------------- prep kernels ----------------
__global__ void k_init() { g_kmin = 0xFFFFFFFFu; g_kmax = 0u; }

// 288 blocks x 256 threads x float4 = 294912 elements exactly
__global__ void k_minmax(const float* __restrict__ w) {
    int idx = (blockIdx.x * 256 + threadIdx.x) * 4;
    float4 v = *(const float4*)(w + idx);
    float lmin = fminf(fminf(v.x, v.y), fminf(v.z, v.w));
    float lmax = fmaxf(fmaxf(v.x, v.y), fmaxf(v.z, v.w));
    unsigned kmin = f2key(lmin), kmax = f2key(lmax);
#pragma unroll
    for (int s = 16; s; s >>= 1) {
        kmin = min(kmin, __shfl_xor_sync(0xffffffffu, kmin, s));
        kmax = max(kmax, __shfl_xor_sync(0xffffffffu, kmax, s));
    }
    __shared__ unsigned smin[8], smax[8];
    int wid = threadIdx.x >> 5;
    if ((threadIdx.x & 31) == 0) { smin[wid] = kmin; smax[wid] = kmax; }
    __syncthreads();
    if (threadIdx.x == 0) {
#pragma unroll
        for (int i = 1; i < 8; i++) { kmin = min(kmin, smin[i]); kmax = max(kmax, smax[i]); }
        atomicMin(&g_kmin, kmin);
        atomicMax(&g_kmax, kmax);
    }
}

// 288 blocks x 1024 threads: quantize w[m][d] -> fp16 (exact small ints)
__global__ void k_quant(const float* __restrict__ w) {
    float wmin = key2f(g_kmin), wmax = key2f(g_kmax);
    float scale = 15.0f / (wmax - wmin + 1e-9f);
    int idx = blockIdx.x * 1024 + threadIdx.x;   // 294912 total
    float q = rintf(w[idx] * scale);
    q = fminf(fmaxf(q, -7.0f), 7.0f);
    g_wqh[idx] = __float2half_rn(q);
    if (idx < DTOT) {
        int c = idx / 9, p = idx - c * 9, di = p / 3, dj = p - di * 3;
        g_tab[idx] = (c * 1024 + di * 32 + dj) | (p << 20);
    }
}

// ---------------- fused HMMA kernel ----------------
// Block tile: 128 pixels x 256 channels (ALL channels -> im2col done once).
// 16 warps (wm = wid&3 pixel subtile of 32, wn = wid>>2 channel subtile of 64).
// grid = 16384/128 = 128 blocks.
#define SLD        72                     // halves per smem row (64 + 8 pad)
#define ROWB       (SLD * 2)              // 144 bytes
#define XH_OFF     0
#define XL_OFF     (128 * ROWB)           // 18432
#define W_OFF      (2 * 128 * ROWB)       // 36864
#define STG_BYTES  (W_OFF + 256 * ROWB)   // 73728
#define SMEM_DYN   (2 * STG_BYTES)        // 147456

// im2col + exact hi/lo fp16 split for one chunk into one stage buffer.
// Lane layout: consecutive lanes = consecutive pixels (coalesced gathers).
__device__ __forceinline__ void convert_x(int c, char* sb, int pix, int lks,
                                          const float* xbase, int vmask) {
    const int* tab = g_tab + c * 64 + lks * 16;
    uint32_t hi[8], lo[8];
#pragma unroll
    for (int t = 0; t < 8; t++) {
        int e0 = tab[2 * t], e1 = tab[2 * t + 1];
        float v0 = ((vmask >> (e0 >> 20)) & 1) ? __ldg(xbase + (e0 & 0xFFFFF)) : 0.0f;
        float v1 = ((vmask >> (e1 >> 20)) & 1) ? __ldg(xbase + (e1 & 0xFFFFF)) : 0.0f;
        __half2 hh = __floats2half2_rn(v0, v1);
        float2 hf = __half22float2(hh);
        __half2 hl = __floats2half2_rn(v0 - hf.x, v1 - hf.y);
        hi[t] = *reinterpret_cast<uint32_t*>(&hh);
        lo[t] = *reinterpret_cast<uint32_t*>(&hl);
    }
    const uint32_t doff = (uint32_t)pix * ROWB + lks * 32;
    *(uint4*)(sb + XH_OFF + doff)      = make_uint4(hi[0], hi[1], hi[2], hi[3]);
    *(uint4*)(sb + XH_OFF + doff + 16) = make_uint4(hi[4], hi[5], hi[6], hi[7]);
    *(uint4*)(sb + XL_OFF + doff)      = make_uint4(lo[0], lo[1], lo[2], lo[3]);
    *(uint4*)(sb + XL_OFF + doff + 16) = make_uint4(lo[4], lo[5], lo[6], lo[7]);
}

__global__ void __launch_bounds__(512, 1)
k_gemm(const float* __restrict__ inp, float* __restrict__ out) {
    extern __shared__ char dyn[];

    const int tid = threadIdx.x, lane = tid & 31, wid = tid >> 5;
    const int bm = blockIdx.x;
    const int b = bm >> 3;
    const int hw0 = (bm & 7) << 7;

    // ---- im2col gather setup (lane = consecutive pixel) ----
    const int pix = tid & 127;
    const int lks = tid >> 7;                       // 0..3 -> k group of 16
    const int hw = hw0 + pix, h = hw >> 5, wc = hw & 31;
    const float* xbase = inp + (size_t)b * (CIN * 1024) + h * 32 + wc - 33;
    int vmask = 0;
#pragma unroll
    for (int di = 0; di < 3; ++di)
#pragma unroll
        for (int dj = 0; dj < 3; ++dj) {
            int hh = h + di - 1, wwp = wc + dj - 1;
            if (hh >= 0 && hh < 32 && wwp >= 0 && wwp < 32)
                vmask |= 1 << (di * 3 + dj);
        }

    // ---- W cp.async mapping: 2048 16B-chunks per chunk-stage, 4 per thread ----
    // chunk q: row = q>>3 (channel), kg = q&7
    const uint32_t dynb = smem_u32(dyn);

    // ---- compute mapping ----
    const int wm = wid & 3, wn = wid >> 2;
    const uint32_t offA = (((wm * 32 + (lane & 15)) * SLD + (lane >> 4) * 8) * 2);
    const uint32_t offB0 = (((wn * 64 + (lane & 15)) * SLD + (lane >> 4) * 8) * 2);

    // prologue: stage chunk 0
    convert_x(0, dyn, pix, lks, xbase, vmask);
#pragma unroll
    for (int i = 0; i < 4; i++) {
        int q = tid + i * 512;
        int row = q >> 3, kg = q & 7;
        CP16(dynb + W_OFF + row * ROWB + kg * 16,
             g_wqh + (size_t)row * DTOT + kg * 8);
    }
    CP_COMMIT();

    uint32_t cnt[16];
#pragma unroll
    for (int j = 0; j < 16; j++) cnt[j] = 0;

#pragma unroll 1
    for (int c = 0; c < RCH; c++) {
        CP_WAIT0();
        __syncthreads();

        const uint32_t sbu = dynb + (c & 1) * STG_BYTES;
        char* sbo = dyn + ((c + 1) & 1) * STG_BYTES;

        // stage W(c+1) (async, overlaps MMAs)
        if (c + 1 < RCH) {
            const uint32_t wdst = smem_u32(sbo) + W_OFF;
            const int koff = (c + 1) * 64;
#pragma unroll
            for (int i = 0; i < 4; i++) {
                int q = tid + i * 512;
                int row = q >> 3, kg = q & 7;
                CP16(wdst + row * ROWB + kg * 16,
                     g_wqh + (size_t)row * DTOT + koff + kg * 8);
            }
            CP_COMMIT();
        }

        // compute chunk c: two channel halves of 32 (keeps acc at 32 regs)
#pragma unroll
        for (int hf = 0; hf < 2; hf++) {
            const uint32_t aAh0 = sbu + XH_OFF + offA, aAh1 = aAh0 + 16 * ROWB;
            const uint32_t aAl0 = sbu + XL_OFF + offA, aAl1 = aAl0 + 16 * ROWB;
            const uint32_t aB0 = sbu + W_OFF + offB0 + hf * (32 * ROWB);
            const uint32_t aB1 = aB0 + 16 * ROWB;

            float acc[2][4][4];
#pragma unroll
            for (int mt = 0; mt < 2; mt++)
#pragma unroll
                for (int nt = 0; nt < 4; nt++)
#pragma unroll
                    for (int e = 0; e < 4; e++) acc[mt][nt][e] = 0.0f;

#pragma unroll
            for (int ks = 0; ks < 4; ks++) {
                const uint32_t off = ks * 32;
                uint32_t ah0[4], ah1[4], al0[4], al1[4], b0[4], b1[4];
                LDSM4(ah0, aAh0 + off);
                LDSM4(ah1, aAh1 + off);
                LDSM4(al0, aAl0 + off);
                LDSM4(al1, aAl1 + off);
                LDSM4(b0, aB0 + off);
                LDSM4(b1, aB1 + off);
                MMA16816(acc[0][0], ah0, b0[0], b0[2]);
                MMA16816(acc[0][1], ah0, b0[1], b0[3]);
                MMA16816(acc[0][2], ah0, b1[0], b1[2]);
                MMA16816(acc[0][3], ah0, b1[1], b1[3]);
                MMA16816(acc[1][0], ah1, b0[0], b0[2]);
                MMA16816(acc[1][1], ah1, b0[1], b0[3]);
                MMA16816(acc[1][2], ah1, b1[0], b1[2]);
                MMA16816(acc[1][3], ah1, b1[1], b1[3]);
                MMA16816(acc[0][0], al0, b0[0], b0[2]);
                MMA16816(acc[0][1], al0, b0[1], b0[3]);
                MMA16816(acc[0][2], al0, b1[0], b1[2]);
                MMA16816(acc[0][3], al0, b1[1], b1[3]);
                MMA16816(acc[1][0], al1, b0[0], b0[2]);
                MMA16816(acc[1][1], al1, b0[1], b0[3]);
                MMA16816(acc[1][2], al1, b1[0], b1[2]);
                MMA16816(acc[1][3], al1, b1[1], b1[3]);
            }

            // threshold (>= 0 -> +1) into packed byte counters
#pragma unroll
            for (int mt = 0; mt < 2; mt++)
#pragma unroll
                for (int nt = 0; nt < 4; nt++)
#pragma unroll
                    for (int e = 0; e < 4; e++) {
                        int idx = hf * 32 + mt * 16 + nt * 4 + e;
                        uint32_t one = (acc[mt][nt][e] >= 0.0f) ? 1u : 0u;
                        cnt[idx >> 2] += one << ((idx & 3) * 8);
                    }
        }

        // convert X(c+1) into the other stage (overlaps tensor drain)
        if (c + 1 < RCH)
            convert_x(c + 1, sbo, pix, lks, xbase, vmask);
    }

    // ---- epilogue: counts -> smem byte transpose -> coalesced float4 stores ----
    __syncthreads();   // all MMAs/LDSMs done; reuse dyn[0..32767] as [chan][pix] bytes
    {
        const int g = lane >> 2, t = lane & 3;
        unsigned char* sb = (unsigned char*)dyn;
#pragma unroll
        for (int hf = 0; hf < 2; hf++)
#pragma unroll
            for (int mt = 0; mt < 2; mt++)
#pragma unroll
                for (int nt = 0; nt < 4; nt++)
#pragma unroll
                    for (int e2 = 0; e2 < 2; e2++)
#pragma unroll
                        for (int e1 = 0; e1 < 2; e1++) {
                            int idx = hf * 32 + mt * 16 + nt * 4 + e2 * 2 + e1;
                            int chan = wn * 64 + hf * 32 + nt * 8 + 2 * t + e1;
                            int pixl = wm * 32 + mt * 16 + g + e2 * 8;
                            sb[chan * 128 + pixl] =
                                (unsigned char)((cnt[idx >> 2] >> ((idx & 3) * 8)) & 0xFF);
                        }
    }
    __syncthreads();
    {
        const uint32_t* sw = (const uint32_t*)dyn;
        float* ob = out + ((size_t)b * COUT << 10) + hw0;
#pragma unroll
        for (int i = 0; i < 16; i++) {
            int w = tid + i * 512;              // word index, 8192 total
            int chan = w >> 5, pixl = (w & 31) * 4;
            uint32_t u = sw[w];
            float4 v = make_float4((float)(u & 0xFF), (float)((u >> 8) & 0xFF),
                                   (float)((u >> 16) & 0xFF), (float)(u >> 24));
            *(float4*)(ob + ((size_t)chan << 10) + pixl) = v;
        }
    }
}

// ---------------- launch ----------------
extern "C" void kernel_launch(void* const* d_in, const int* in_sizes, int n_in,
                              void* d_out, int out_size) {
    const float* inp = (const float*)d_in[0];  // [16,128,32,32]
    const float* wt  = (const float*)d_in[1];  // [256,128,3,3]
    float* out = (float*)d_out;                // [16,256,32,32]

    cudaFuncSetAttribute(k_gemm, cudaFuncAttributeMaxDynamicSharedMemorySize, SMEM_DYN);

    k_init<<<1, 1>>>();
    k_minmax<<<288, 256>>>(wt);
    k_quant<<<288, 1024>>>(wt);
    k_gemm<<<128, 512, SMEM_DYN>>>(inp, out);
}

// round 10
// speedup vs baseline: 1.7635x; 1.0293x over previous
#include <cuda_runtime.h>
#include <cuda_fp16.h>
#include <cstdint>

// Problem constants
#define CIN   128
#define COUT  256
#define DTOT  1152     // 18 chunks * 64
#define RCH   18
#define NPIX  16384

// ---------------- device scratch (no cudaMalloc allowed) ----------------
__device__ __half   g_wqh[COUT * DTOT];   // quantized weight fp16 [m][d]
__device__ int      g_tab[DTOT];          // packed im2col offsets: off | (p<<20)
__device__ unsigned g_kmin, g_kmax;

// ---------------- helpers ----------------
__device__ __forceinline__ unsigned f2key(float f) {
    unsigned u = __float_as_uint(f);
    return (u & 0x80000000u) ? ~u : (u | 0x80000000u);
}
__device__ __forceinline__ float key2f(unsigned k) {
    unsigned u = (k & 0x80000000u) ? (k ^ 0x80000000u) : ~k;
    return __uint_as_float(u);
}
__device__ __forceinline__ uint32_t smem_u32(const void* p) {
    uint32_t a;
    asm("{ .reg .u64 t; cvta.to.shared.u64 t, %1; cvt.u32.u64 %0, t; }" : "=r"(a) : "l"(p));
    return a;
}

#define LDSM4(r, addr)                                                         \
    asm volatile("ldmatrix.sync.aligned.m8n8.x4.shared.b16 {%0,%1,%2,%3},[%4];"\
        : "=r"((r)[0]), "=r"((r)[1]), "=r"((r)[2]), "=r"((r)[3]) : "r"(addr))

#define MMA16816(c, a, b0v, b1v)                                               \
    asm volatile("mma.sync.aligned.m16n8k16.row.col.f32.f16.f16.f32 "          \
        "{%0,%1,%2,%3},{%4,%5,%6,%7},{%8,%9},{%0,%1,%2,%3};"                   \
        : "+f"((c)[0]), "+f"((c)[1]), "+f"((c)[2]), "+f"((c)[3])               \
        : "r"((a)[0]), "r"((a)[1]), "r"((a)[2]), "r"((a)[3]),                  \
          "r"(b0v), "r"(b1v))

#define CP16(dst, src)                                                         \
    asm volatile("cp.async.cg.shared.global [%0], [%1], 16;"                   \
        :: "r"(dst), "l"(src) : "memory")

#define MBAR_INIT(addr, cnt) \
    asm volatile("mbarrier.init.shared.b64 [%0], %1;" :: "r"(addr), "r"(cnt) : "memory")
#define MBAR_ARRIVE(addr) \
    asm volatile("mbarrier.arrive.shared.b64 _, [%0];" :: "r"(addr) : "memory")
#define CP_ARRIVE_NOINC(addr) \
    asm volatile("cp.async.mbarrier.arrive.noinc.shared.b64 [%0];" :: "r"(addr) : "memory")

__device__ __forceinline__ void mbar_wait(uint32_t mbar, uint32_t parity) {
    asm volatile(
        "{\n\t.reg .pred P;\n\t"
        "LAB_WAIT_%=:\n\t"
        "mbarrier.try_wait.parity.acquire.cta.shared::cta.b64 P, [%0], %1, 0x989680;\n\t"
        "@P bra.uni LAB_DONE_%=;\n\t"
        "bra.uni LAB_WAIT_%=;\n\t"
        "LAB_DONE_%=:\n\t}"
        :: "r"(mbar), "r"(parity) : "memory");
}

// ---------------- prep kernels ----------------
__global__ void k_init() { g_kmin = 0xFFFFFFFFu; g_kmax = 0u; }

// 288 blocks x 256 threads x float4 = 294912 elements exactly
__global__ void k_minmax(const float* __restrict__ w) {
    int idx = (blockIdx.x * 256 + threadIdx.x) * 4;
    float4 v = *(const float4*)(w + idx);
    float lmin = fminf(fminf(v.x, v.y), fminf(v.z, v.w));
    float lmax = fmaxf(fmaxf(v.x, v.y), fmaxf(v.z, v.w));
    unsigned kmin = f2key(lmin), kmax = f2key(lmax);
#pragma unroll
    for (int s = 16; s; s >>= 1) {
        kmin = min(kmin, __shfl_xor_sync(0xffffffffu, kmin, s));
        kmax = max(kmax, __shfl_xor_sync(0xffffffffu, kmax, s));
    }
    __shared__ unsigned smin[8], smax[8];
    int wid = threadIdx.x >> 5;
    if ((threadIdx.x & 31) == 0) { smin[wid] = kmin; smax[wid] = kmax; }
    __syncthreads();
    if (threadIdx.x == 0) {
#pragma unroll
        for (int i = 1; i < 8; i++) { kmin = min(kmin, smin[i]); kmax = max(kmax, smax[i]); }
        atomicMin(&g_kmin, kmin);
        atomicMax(&g_kmax, kmax);
    }
}

// 288 blocks x 1024 threads: quantize w[m][d] -> fp16 (exact small ints)
__global__ void k_quant(const float* __restrict__ w) {
    float wmin = key2f(g_kmin), wmax = key2f(g_kmax);
    float scale = 15.0f / (wmax - wmin + 1e-9f);
    int idx = blockIdx.x * 1024 + threadIdx.x;   // 294912 total
    float q = rintf(w[idx] * scale);
    q = fminf(fmaxf(q, -7.0f), 7.0f);
    g_wqh[idx] = __float2half_rn(q);
    if (idx < DTOT) {
        int c = idx / 9, p = idx - c * 9, di = p / 3, dj = p - di * 3;
        g_tab[idx] = (c * 1024 + di * 32 + dj) | (p << 20);
    }
}

// ---------------- fused warp-specialized HMMA kernel ----------------
// Block tile: 128 pixels x 256 channels. grid = 128 blocks, 640 threads.
// Warps 0-15: consumers (4x4, warp tile 32x64). Warps 16-19: producers.
#define SLD        72                     // halves per smem row (64 + 8 pad)
#define ROWB       (SLD * 2)              // 144 bytes
#define XH_OFF     0
#define XL_OFF     (128 * ROWB)           // 18432
#define W_OFF      (2 * 128 * ROWB)       // 36864
#define STG_BYTES  (W_OFF + 256 * ROWB)   // 73728
#define SMEM_DYN   (2 * STG_BYTES)        // 147456

__global__ void __launch_bounds__(640, 1)
k_gemm(const float* __restrict__ inp, float* __restrict__ out) {
    extern __shared__ char dyn[];
    __shared__ __align__(8) unsigned long long s_full[2], s_empty[2];

    const int tid = threadIdx.x, lane = tid & 31, wid = tid >> 5;
    const int bm = blockIdx.x;
    const int b = bm >> 3;
    const int hw0 = (bm & 7) << 7;
    const uint32_t dynb = smem_u32(dyn);
    const uint32_t mbf0 = smem_u32(&s_full[0]), mbf1 = smem_u32(&s_full[1]);
    const uint32_t mbe0 = smem_u32(&s_empty[0]), mbe1 = smem_u32(&s_empty[1]);

    if (tid == 0) {
        MBAR_INIT(mbf0, 256);   // 128 producer STS-arrivals + 128 cp-arrivals
        MBAR_INIT(mbf1, 256);
        MBAR_INIT(mbe0, 512);   // consumer threads
        MBAR_INIT(mbe1, 512);
    }
    __syncthreads();

    if (wid >= 16) {
        // ================= PRODUCER (warps 16-19, 128 threads) =================
        const int pix = tid - 512;               // one pixel per thread
        const int hw = hw0 + pix, h = hw >> 5, wc = hw & 31;
        const float* xbase = inp + (size_t)b * (CIN * 1024) + h * 32 + wc - 33;
        int vmask = 0;
#pragma unroll
        for (int di = 0; di < 3; ++di)
#pragma unroll
            for (int dj = 0; dj < 3; ++dj) {
                int hh = h + di - 1, wwp = wc + dj - 1;
                if (hh >= 0 && hh < 32 && wwp >= 0 && wwp < 32)
                    vmask |= 1 << (di * 3 + dj);
            }

#pragma unroll 1
        for (int c = 0; c < RCH; c++) {
            const int s = c & 1;
            if (c >= 2) mbar_wait(s ? mbe1 : mbe0, ((c >> 1) + 1) & 1);
            char* sb = dyn + s * STG_BYTES;
            const int* tab = g_tab + c * 64;

            // X: 64 k's for this pixel, in 8 groups of 8
#pragma unroll
            for (int g = 0; g < 8; g++) {
                uint32_t hi4[4], lo4[4];
#pragma unroll
                for (int t = 0; t < 4; t++) {
                    int e0 = tab[g * 8 + 2 * t], e1 = tab[g * 8 + 2 * t + 1];
                    float v0 = ((vmask >> (e0 >> 20)) & 1) ? __ldg(xbase + (e0 & 0xFFFFF)) : 0.0f;
                    float v1 = ((vmask >> (e1 >> 20)) & 1) ? __ldg(xbase + (e1 & 0xFFFFF)) : 0.0f;
                    __half2 hh = __floats2half2_rn(v0, v1);
                    float2 hf = __half22float2(hh);
                    __half2 hl = __floats2half2_rn(v0 - hf.x, v1 - hf.y);
                    hi4[t] = *reinterpret_cast<uint32_t*>(&hh);
                    lo4[t] = *reinterpret_cast<uint32_t*>(&hl);
                }
                const uint32_t doff = (uint32_t)pix * ROWB + g * 16;
                *(uint4*)(sb + XH_OFF + doff) = make_uint4(hi4[0], hi4[1], hi4[2], hi4[3]);
                *(uint4*)(sb + XL_OFF + doff) = make_uint4(lo4[0], lo4[1], lo4[2], lo4[3]);
            }
            MBAR_ARRIVE(s ? mbf1 : mbf0);   // release: publishes the X STS

            // W: 2048 16B chunks / 128 threads = 16 cp.async each
            const uint32_t wdst = dynb + s * STG_BYTES + W_OFF;
#pragma unroll
            for (int i = 0; i < 16; i++) {
                int q = pix + i * 128, row = q >> 3, kg = q & 7;
                CP16(wdst + row * ROWB + kg * 16,
                     g_wqh + (size_t)row * DTOT + c * 64 + kg * 8);
            }
            CP_ARRIVE_NOINC(s ? mbf1 : mbf0);
        }
        // producers fall through to kernel end
    } else {
        // ================= CONSUMER (warps 0-15, 512 threads) =================
        const int wm = wid & 3, wn = wid >> 2;
        const uint32_t offA = (((wm * 32 + (lane & 15)) * SLD + (lane >> 4) * 8) * 2);
        const uint32_t offB0 = (((wn * 64 + (lane & 15)) * SLD + (lane >> 4) * 8) * 2);

        uint32_t cnt[16];
#pragma unroll
        for (int j = 0; j < 16; j++) cnt[j] = 0;

#pragma unroll 1
        for (int c = 0; c < RCH; c++) {
            const int s = c & 1;
            mbar_wait(s ? mbf1 : mbf0, (c >> 1) & 1);
            const uint32_t sbu = dynb + s * STG_BYTES;

#pragma unroll
            for (int hf = 0; hf < 2; hf++) {
                const uint32_t aAh0 = sbu + XH_OFF + offA, aAh1 = aAh0 + 16 * ROWB;
                const uint32_t aAl0 = sbu + XL_OFF + offA, aAl1 = aAl0 + 16 * ROWB;
                const uint32_t aB0 = sbu + W_OFF + offB0 + hf * (32 * ROWB);
                const uint32_t aB1 = aB0 + 16 * ROWB;

                float acc[2][4][4];
#pragma unroll
                for (int mt = 0; mt < 2; mt++)
#pragma unroll
                    for (int nt = 0; nt < 4; nt++)
#pragma unroll
                        for (int e = 0; e < 4; e++) acc[mt][nt][e] = 0.0f;

#pragma unroll
                for (int ks = 0; ks < 4; ks++) {
                    const uint32_t off = ks * 32;
                    uint32_t ah0[4], ah1[4], al0[4], al1[4], b0[4], b1[4];
                    LDSM4(ah0, aAh0 + off);
                    LDSM4(ah1, aAh1 + off);
                    LDSM4(al0, aAl0 + off);
                    LDSM4(al1, aAl1 + off);
                    LDSM4(b0, aB0 + off);
                    LDSM4(b1, aB1 + off);
                    MMA16816(acc[0][0], ah0, b0[0], b0[2]);
                    MMA16816(acc[0][1], ah0, b0[1], b0[3]);
                    MMA16816(acc[0][2], ah0, b1[0], b1[2]);
                    MMA16816(acc[0][3], ah0, b1[1], b1[3]);
                    MMA16816(acc[1][0], ah1, b0[0], b0[2]);
                    MMA16816(acc[1][1], ah1, b0[1], b0[3]);
                    MMA16816(acc[1][2], ah1, b1[0], b1[2]);
                    MMA16816(acc[1][3], ah1, b1[1], b1[3]);
                    MMA16816(acc[0][0], al0, b0[0], b0[2]);
                    MMA16816(acc[0][1], al0, b0[1], b0[3]);
                    MMA16816(acc[0][2], al0, b1[0], b1[2]);
                    MMA16816(acc[0][3], al0, b1[1], b1[3]);
                    MMA16816(acc[1][0], al1, b0[0], b0[2]);
                    MMA16816(acc[1][1], al1, b0[1], b0[3]);
                    MMA16816(acc[1][2], al1, b1[0], b1[2]);
                    MMA16816(acc[1][3], al1, b1[1], b1[3]);
                }

#pragma unroll
                for (int mt = 0; mt < 2; mt++)
#pragma unroll
                    for (int nt = 0; nt < 4; nt++)
#pragma unroll
                        for (int e = 0; e < 4; e++) {
                            int idx = hf * 32 + mt * 16 + nt * 4 + e;
                            uint32_t one = (acc[mt][nt][e] >= 0.0f) ? 1u : 0u;
                            cnt[idx >> 2] += one << ((idx & 3) * 8);
                        }
            }
            MBAR_ARRIVE(s ? mbe1 : mbe0);   // release: LDSM reads of stage s done
        }

        // ---- epilogue (consumers only): byte transpose -> coalesced stores ----
        asm volatile("bar.sync 1, 512;" ::: "memory");
        {
            const int g = lane >> 2, t = lane & 3;
            unsigned char* sb = (unsigned char*)dyn;
#pragma unroll
            for (int hf = 0; hf < 2; hf++)
#pragma unroll
                for (int mt = 0; mt < 2; mt++)
#pragma unroll
                    for (int nt = 0; nt < 4; nt++)
#pragma unroll
                        for (int e2 = 0; e2 < 2; e2++)
#pragma unroll
                            for (int e1 = 0; e1 < 2; e1++) {
                                int idx = hf * 32 + mt * 16 + nt * 4 + e2 * 2 + e1;
                                int chan = wn * 64 + hf * 32 + nt * 8 + 2 * t + e1;
                                int pixl = wm * 32 + mt * 16 + g + e2 * 8;
                                sb[chan * 128 + pixl] =
                                    (unsigned char)((cnt[idx >> 2] >> ((idx & 3) * 8)) & 0xFF);
                            }
        }
        asm volatile("bar.sync 1, 512;" ::: "memory");
        {
            const uint32_t* sw = (const uint32_t*)dyn;
            float* ob = out + ((size_t)b * COUT << 10) + hw0;
#pragma unroll
            for (int i = 0; i < 16; i++) {
                int w = tid + i * 512;              // word index, 8192 total
                int chan = w >> 5, pixl = (w & 31) * 4;
                uint32_t u = sw[w];
                float4 v = make_float4((float)(u & 0xFF), (float)((u >> 8) & 0xFF),
                                       (float)((u >> 16) & 0xFF), (float)(u >> 24));
                *(float4*)(ob + ((size_t)chan << 10) + pixl) = v;
            }
        }
    }
}

// ---------------- launch ----------------
extern "C" void kernel_launch(void* const* d_in, const int* in_sizes, int n_in,
                              void* d_out, int out_size) {
    const float* inp = (const float*)d_in[0];  // [16,128,32,32]
    const float* wt  = (const float*)d_in[1];  // [256,128,3,3]
    float* out = (float*)d_out;                // [16,256,32,32]

    cudaFuncSetAttribute(k_gemm, cudaFuncAttributeMaxDynamicSharedMemorySize, SMEM_DYN);

    k_init<<<1, 1>>>();
    k_minmax<<<288, 256>>>(wt);
    k_quant<<<288, 1024>>>(wt);
    k_gemm<<<128, 640, SMEM_DYN>>>(inp, out);
}